// round 2
// baseline (speedup 1.0000x reference)
#include <cuda_runtime.h>
#include <cstdint>
#include <cstddef>

#define N_NODES 50000
#define N_EDGES 800000
#define FDIM 256

// ---------------- device scratch (allocation-free rule: __device__ globals) ---------
__device__ int   g_is64;                         // edge_index dtype flag
__device__ float g_deg[N_NODES];                 // degree, then deg^-1/2 in place
__device__ int   g_cnt[N_NODES];                 // per-row edge count
__device__ int   g_rowptr[N_NODES + 1];          // CSR row pointers
__device__ int   g_cursor[N_NODES];              // scatter cursors
__device__ int   g_cola[N_EDGES];                // CSR column indices
__device__ float g_wa[N_EDGES];                  // CSR normalized weights
__device__ float g_y[(size_t)N_NODES * FDIM];    // y = x @ W^T   (51.2 MB)

// ---------------- f32x2 packed-FMA helpers (PTX; sm_100+) ---------------------------
__device__ __forceinline__ unsigned long long pack2(float lo, float hi) {
    unsigned long long r;
    asm("mov.b64 %0, {%1, %2};" : "=l"(r) : "f"(lo), "f"(hi));
    return r;
}
__device__ __forceinline__ float2 unpack2(unsigned long long v) {
    float2 r;
    asm("mov.b64 {%0, %1}, %2;" : "=f"(r.x), "=f"(r.y) : "l"(v));
    return r;
}
__device__ __forceinline__ void fma2(unsigned long long& d, unsigned long long a,
                                     unsigned long long b) {
    asm("fma.rn.f32x2 %0, %1, %2, %3;" : "=l"(d) : "l"(a), "l"(b), "l"(d));
}

// ---------------- edge-index access (int32 vs int64, runtime-detected) --------------
__device__ __forceinline__ int edge_at(const void* ei, int idx, int is64) {
    int v = is64 ? (int)((const long long*)ei)[idx] : ((const int*)ei)[idx];
    if ((unsigned)v >= (unsigned)N_NODES) v = 0;   // defensive: no trap, measurable err
    return v;
}

// ---------------- kernels -----------------------------------------------------------

// Detect dtype: for int64 (values < 2^31) all odd 32-bit words are 0.
__global__ void k_detect(const int* __restrict__ w) {
    __shared__ int cnt;
    int t = threadIdx.x;
    if (t == 0) cnt = 0;
    __syncthreads();
    if (w[2 * t + 1] == 0) atomicAdd(&cnt, 1);
    __syncthreads();
    if (t == 0) g_is64 = (cnt > 900) ? 1 : 0;
}

__global__ void k_zero() {
    int i = blockIdx.x * blockDim.x + threadIdx.x;
    if (i < N_NODES) { g_deg[i] = 0.0f; g_cnt[i] = 0; }
}

// degree (weighted row-sum) + per-row edge counts
__global__ void k_deg(const void* __restrict__ ei, const float* __restrict__ C) {
    int e = blockIdx.x * blockDim.x + threadIdx.x;
    if (e < N_EDGES) {
        int is64 = g_is64;
        int r = edge_at(ei, e, is64);
        atomicAdd(&g_deg[r], C[e]);
        atomicAdd(&g_cnt[r], 1);
    }
}

__global__ void k_dis() {
    int i = blockIdx.x * blockDim.x + threadIdx.x;
    if (i < N_NODES) {
        float d = g_deg[i];
        g_deg[i] = (d > 0.0f) ? rsqrtf(d) : 0.0f;
    }
}

// single-block exclusive scan of g_cnt -> g_rowptr / g_cursor
__global__ void k_scan() {
    __shared__ int s[1024];
    int t = threadIdx.x;
    int carry = 0;
    for (int base = 0; base < N_NODES; base += 1024) {
        int idx = base + t;
        int v = (idx < N_NODES) ? g_cnt[idx] : 0;
        int orig = v;
        s[t] = v;
        __syncthreads();
        for (int off = 1; off < 1024; off <<= 1) {
            int add = (t >= off) ? s[t - off] : 0;
            __syncthreads();
            s[t] += add;
            __syncthreads();
        }
        int excl = s[t] - orig;
        if (idx < N_NODES) { g_rowptr[idx] = carry + excl; g_cursor[idx] = carry + excl; }
        carry += s[1023];
        __syncthreads();
    }
    if (t == 0) g_rowptr[N_NODES] = carry;  // == N_EDGES
}

// scatter edges into CSR with normalized weight w = dis[row]*C*dis[col]
__global__ void k_scatter(const void* __restrict__ ei, const float* __restrict__ C) {
    int e = blockIdx.x * blockDim.x + threadIdx.x;
    if (e < N_EDGES) {
        int is64 = g_is64;
        int r = edge_at(ei, e, is64);
        int c = edge_at(ei, N_EDGES + e, is64);
        float w = g_deg[r] * C[e] * g_deg[c];
        int p = atomicAdd(&g_cursor[r], 1);
        g_cola[p] = c;
        g_wa[p]   = w;
    }
}

// y = x @ W^T  (M x 256 @ 256 x 256), 128x128x32 tiles, 8x8/thread, f32x2 FMA
__global__ void __launch_bounds__(256, 2) k_gemm(const float* __restrict__ X,
                                                 const float* __restrict__ W) {
    __shared__ __align__(16) float As[32][132];   // [k][m], pad 132 (16B-aligned rows)
    __shared__ __align__(16) float Bs[32][132];   // [k][n]
    int tid = threadIdx.x;
    int rowBase = blockIdx.x * 128;
    int colBase = blockIdx.y * 128;
    int tx = tid & 15;          // N-dim thread coord (8 cols each)
    int ty = tid >> 4;          // M-dim thread coord (8 rows each)

    unsigned long long acc[8][4];
    #pragma unroll
    for (int i = 0; i < 8; i++)
        #pragma unroll
        for (int j = 0; j < 4; j++) acc[i][j] = 0ull;

    for (int k0 = 0; k0 < 256; k0 += 32) {
        #pragma unroll
        for (int i = 0; i < 4; i++) {
            int v  = tid + i * 256;   // 1024 float4 slots
            int r  = v >> 3;          // 0..127 tile row
            int kq = v & 7;           // 0..7 (k quad)
            int grow = rowBase + r;
            float4 a4 = make_float4(0.f, 0.f, 0.f, 0.f);
            if (grow < N_NODES)
                a4 = *(const float4*)(X + (size_t)grow * 256 + k0 + kq * 4);
            As[kq * 4 + 0][r] = a4.x; As[kq * 4 + 1][r] = a4.y;
            As[kq * 4 + 2][r] = a4.z; As[kq * 4 + 3][r] = a4.w;
            float4 b4 = *(const float4*)(W + (size_t)(colBase + r) * 256 + k0 + kq * 4);
            Bs[kq * 4 + 0][r] = b4.x; Bs[kq * 4 + 1][r] = b4.y;
            Bs[kq * 4 + 2][r] = b4.z; Bs[kq * 4 + 3][r] = b4.w;
        }
        __syncthreads();

        #pragma unroll
        for (int kk = 0; kk < 32; kk++) {
            float4 a0 = *(const float4*)&As[kk][ty * 8];
            float4 a1 = *(const float4*)&As[kk][ty * 8 + 4];
            ulonglong2 b0 = *(const ulonglong2*)&Bs[kk][tx * 8];
            ulonglong2 b1 = *(const ulonglong2*)&Bs[kk][tx * 8 + 4];
            unsigned long long bv0 = b0.x, bv1 = b0.y, bv2 = b1.x, bv3 = b1.y;
            float av[8] = {a0.x, a0.y, a0.z, a0.w, a1.x, a1.y, a1.z, a1.w};
            #pragma unroll
            for (int i = 0; i < 8; i++) {
                unsigned long long ap = pack2(av[i], av[i]);
                fma2(acc[i][0], ap, bv0);
                fma2(acc[i][1], ap, bv1);
                fma2(acc[i][2], ap, bv2);
                fma2(acc[i][3], ap, bv3);
            }
        }
        __syncthreads();
    }

    #pragma unroll
    for (int i = 0; i < 8; i++) {
        int grow = rowBase + ty * 8 + i;
        if (grow < N_NODES) {
            float* yp = g_y + (size_t)grow * 256 + colBase + tx * 8;
            float2 p0 = unpack2(acc[i][0]), p1 = unpack2(acc[i][1]);
            float2 p2 = unpack2(acc[i][2]), p3 = unpack2(acc[i][3]);
            *(float4*)(yp)     = make_float4(p0.x, p0.y, p1.x, p1.y);
            *(float4*)(yp + 4) = make_float4(p2.x, p2.y, p3.x, p3.y);
        }
    }
}

// out[i,:] = sum_{e in row i} w[e] * y[col[e],:] + b   — one block per node, no atomics
__global__ void __launch_bounds__(256) k_agg(const float* __restrict__ bias,
                                             float* __restrict__ out) {
    int i = blockIdx.x;
    int f = threadIdx.x;
    int s = g_rowptr[i];
    int e = g_rowptr[i + 1];
    float acc = 0.0f;
    int p = s;
    for (; p + 4 <= e; p += 4) {
        int c0 = g_cola[p], c1 = g_cola[p + 1], c2 = g_cola[p + 2], c3 = g_cola[p + 3];
        float w0 = g_wa[p], w1 = g_wa[p + 1], w2 = g_wa[p + 2], w3 = g_wa[p + 3];
        acc += w0 * g_y[(size_t)c0 * FDIM + f];
        acc += w1 * g_y[(size_t)c1 * FDIM + f];
        acc += w2 * g_y[(size_t)c2 * FDIM + f];
        acc += w3 * g_y[(size_t)c3 * FDIM + f];
    }
    for (; p < e; p++)
        acc += g_wa[p] * g_y[(size_t)g_cola[p] * FDIM + f];
    out[(size_t)i * FDIM + f] = acc + bias[f];
}

// ---------------- launch -------------------------------------------------------------
extern "C" void kernel_launch(void* const* d_in, const int* in_sizes, int n_in,
                              void* d_out, int out_size) {
    // Identify inputs by element count (all distinct for this problem).
    const float* x = nullptr;   // 12,800,000
    const void*  ei = nullptr;  //  1,600,000 (int32 or int64 — detected on device)
    const float* C = nullptr;   //    800,000
    const float* W = nullptr;   //     65,536
    const float* b = nullptr;   //        256
    for (int i = 0; i < n_in; i++) {
        switch (in_sizes[i]) {
            case 12800000: x  = (const float*)d_in[i]; break;
            case  1600000: ei = d_in[i];               break;
            case   800000: C  = (const float*)d_in[i]; break;
            case    65536: W  = (const float*)d_in[i]; break;
            case      256: b  = (const float*)d_in[i]; break;
            default: break;
        }
    }
    float* out = (float*)d_out;  // [50000,256] float32

    const int TB = 256;
    k_detect<<<1, 1024>>>((const int*)ei);
    k_zero<<<(N_NODES + TB - 1) / TB, TB>>>();
    k_deg<<<(N_EDGES + TB - 1) / TB, TB>>>(ei, C);
    k_dis<<<(N_NODES + TB - 1) / TB, TB>>>();
    k_scan<<<1, 1024>>>();
    k_scatter<<<(N_EDGES + TB - 1) / TB, TB>>>(ei, C);

    dim3 gg((N_NODES + 127) / 128, FDIM / 128);
    k_gemm<<<gg, 256>>>(x, W);

    k_agg<<<N_NODES, 256>>>(b, out);
}

// round 4
// speedup vs baseline: 1.3401x; 1.3401x over previous
#include <cuda_runtime.h>
#include <cuda_bf16.h>
#include <cstdint>
#include <cstddef>

#define N_NODES 50000
#define N_EDGES 800000
#define FDIM 256

// ================= device scratch ===================================================
__device__ int   g_is64;
__device__ float g_deg[N_NODES];
__device__ int   g_cnt[N_NODES];
__device__ int   g_rowptr[N_NODES + 1];
__device__ int   g_cursor[N_NODES];
__device__ int   g_cola[N_EDGES];
__device__ float g_wa[N_EDGES];
__device__ float g_y[(size_t)N_NODES * FDIM];            // y = x @ W^T (51.2 MB)
__device__ __nv_bfloat16 g_xhi[(size_t)N_NODES * FDIM];
__device__ __nv_bfloat16 g_xlo[(size_t)N_NODES * FDIM];
__device__ __nv_bfloat16 g_whi[FDIM * FDIM];             // [n][k]
__device__ __nv_bfloat16 g_wlo[FDIM * FDIM];

// ================= PTX helpers ======================================================
__device__ __forceinline__ uint32_t smem_u32(const void* p) {
    uint32_t a;
    asm("{ .reg .u64 t; cvta.to.shared.u64 t, %1; cvt.u32.u64 %0, t; }" : "=r"(a) : "l"(p));
    return a;
}
__device__ __forceinline__ void cpa16(uint32_t dst, const void* src, int src_sz) {
    asm volatile("cp.async.cg.shared.global [%0], [%1], 16, %2;"
                 :: "r"(dst), "l"(src), "r"(src_sz));
}
#define CPA_COMMIT() asm volatile("cp.async.commit_group;" ::: "memory")
template <int N>
__device__ __forceinline__ void cpa_wait() {
    asm volatile("cp.async.wait_group %0;" :: "n"(N) : "memory");
}
__device__ __forceinline__ void ldm_x4(uint32_t* r, uint32_t addr) {
    asm volatile("ldmatrix.sync.aligned.m8n8.x4.shared.b16 {%0,%1,%2,%3}, [%4];"
                 : "=r"(r[0]), "=r"(r[1]), "=r"(r[2]), "=r"(r[3]) : "r"(addr));
}
__device__ __forceinline__ void mma_bf16(float* d, const uint32_t* a, const uint32_t* b) {
    asm volatile("mma.sync.aligned.m16n8k16.row.col.f32.bf16.bf16.f32 "
                 "{%0,%1,%2,%3}, {%4,%5,%6,%7}, {%8,%9}, {%0,%1,%2,%3};"
                 : "+f"(d[0]), "+f"(d[1]), "+f"(d[2]), "+f"(d[3])
                 : "r"(a[0]), "r"(a[1]), "r"(a[2]), "r"(a[3]), "r"(b[0]), "r"(b[1]));
}

// ================= edge-index access ================================================
__device__ __forceinline__ int edge_at(const void* ei, int idx, int is64) {
    int v = is64 ? (int)((const long long*)ei)[idx] : ((const int*)ei)[idx];
    if ((unsigned)v >= (unsigned)N_NODES) v = 0;
    return v;
}

// ================= graph-side kernels ==============================================
__global__ void k_detect(const int* __restrict__ w) {
    __shared__ int cnt;
    int t = threadIdx.x;
    if (t == 0) cnt = 0;
    __syncthreads();
    if (w[2 * t + 1] == 0) atomicAdd(&cnt, 1);
    __syncthreads();
    if (t == 0) g_is64 = (cnt > 900) ? 1 : 0;
}

__global__ void k_zero() {
    int i = blockIdx.x * blockDim.x + threadIdx.x;
    if (i < N_NODES) { g_deg[i] = 0.0f; g_cnt[i] = 0; }
}

__global__ void k_deg(const void* __restrict__ ei, const float* __restrict__ C) {
    int e = blockIdx.x * blockDim.x + threadIdx.x;
    if (e < N_EDGES) {
        int is64 = g_is64;
        int r = edge_at(ei, e, is64);
        atomicAdd(&g_deg[r], C[e]);
        atomicAdd(&g_cnt[r], 1);
    }
}

__global__ void k_dis() {
    int i = blockIdx.x * blockDim.x + threadIdx.x;
    if (i < N_NODES) {
        float d = g_deg[i];
        g_deg[i] = (d > 0.0f) ? rsqrtf(d) : 0.0f;
    }
}

// warp-shuffle hierarchical scan, single block of 1024
__global__ void k_scan() {
    __shared__ int wsum[32];
    int t = threadIdx.x, lane = t & 31, wid = t >> 5;
    int carry = 0;
    for (int base = 0; base < N_NODES; base += 1024) {
        int idx = base + t;
        int v = (idx < N_NODES) ? g_cnt[idx] : 0;
        int inc = v;
        #pragma unroll
        for (int off = 1; off < 32; off <<= 1) {
            int n = __shfl_up_sync(0xFFFFFFFFu, inc, off);
            if (lane >= off) inc += n;
        }
        if (lane == 31) wsum[wid] = inc;
        __syncthreads();
        if (wid == 0) {
            int s = wsum[lane];
            #pragma unroll
            for (int off = 1; off < 32; off <<= 1) {
                int n = __shfl_up_sync(0xFFFFFFFFu, s, off);
                if (lane >= off) s += n;
            }
            wsum[lane] = s;
        }
        __syncthreads();
        int woff = (wid > 0) ? wsum[wid - 1] : 0;
        int excl = carry + woff + inc - v;
        if (idx < N_NODES) { g_rowptr[idx] = excl; g_cursor[idx] = excl; }
        carry += wsum[31];
        __syncthreads();
    }
    if (t == 0) g_rowptr[N_NODES] = carry;
}

__global__ void k_scatter(const void* __restrict__ ei, const float* __restrict__ C) {
    int e = blockIdx.x * blockDim.x + threadIdx.x;
    if (e < N_EDGES) {
        int is64 = g_is64;
        int r = edge_at(ei, e, is64);
        int c = edge_at(ei, N_EDGES + e, is64);
        float w = g_deg[r] * C[e] * g_deg[c];
        int p = atomicAdd(&g_cursor[r], 1);
        g_cola[p] = c;
        g_wa[p]   = w;
    }
}

// ================= bf16 hi/lo conversions ==========================================
__global__ void k_cvt_x(const float4* __restrict__ X) {
    int i = blockIdx.x * blockDim.x + threadIdx.x;
    if (i < (N_NODES * FDIM) / 4) {
        float4 v = X[i];
        float f[4] = {v.x, v.y, v.z, v.w};
        ushort4 hv, lv;
        unsigned short* hp = &hv.x;
        unsigned short* lp = &lv.x;
        #pragma unroll
        for (int j = 0; j < 4; j++) {
            __nv_bfloat16 h = __float2bfloat16_rn(f[j]);
            __nv_bfloat16 l = __float2bfloat16_rn(f[j] - __bfloat162float(h));
            hp[j] = *(unsigned short*)&h;
            lp[j] = *(unsigned short*)&l;
        }
        ((ushort4*)g_xhi)[i] = hv;
        ((ushort4*)g_xlo)[i] = lv;
    }
}

__global__ void k_cvt_w(const float* __restrict__ W) {
    int idx = blockIdx.x * blockDim.x + threadIdx.x;
    if (idx < FDIM * FDIM) {
        float w = W[idx];
        __nv_bfloat16 h = __float2bfloat16_rn(w);
        __nv_bfloat16 l = __float2bfloat16_rn(w - __bfloat162float(h));
        g_whi[idx] = h;
        g_wlo[idx] = l;
    }
}

// ================= HMMA GEMM: y = x @ W^T (bf16 hi/lo, m16n8k16) ====================
// grid (391, 2), block 256 (8 warps: warp_m=wid&3 -> 32 rows, warp_n=wid>>2 -> 64 cols)
// smem: A [2 stages][2 planes][128 rows][stride 80B], B same at +40960. Total 80 KB.
#define GSTRIDE 80
#define B_BASE  40960
#define SM_GEMM 81920

__global__ void __launch_bounds__(256, 1) k_gemm_mma() {
    extern __shared__ __align__(128) unsigned char sm[];
    uint32_t sb = smem_u32(sm);
    int tid = threadIdx.x, wid = tid >> 5, lane = tid & 31;
    int warp_m = wid & 3, warp_n = wid >> 2;
    int rowBase = blockIdx.x * 128, colBase = blockIdx.y * 128;

    float acc[2][8][4];
    #pragma unroll
    for (int a = 0; a < 2; a++)
        #pragma unroll
        for (int b = 0; b < 8; b++)
            #pragma unroll
            for (int c = 0; c < 4; c++) acc[a][b][c] = 0.0f;

    int r0 = tid >> 2, c0 = tid & 3;            // thread's 16B-unit coords (2 rows/thread pass)
    // each chunk: 128 rows x 4 units per plane-matrix; 256 threads -> 2 iters

    #define LOAD_CHUNK(kc, stage)                                                      \
    do {                                                                               \
        int _k0 = (kc) * 32;                                                           \
        _Pragma("unroll")                                                              \
        for (int pl = 0; pl < 2; pl++) {                                               \
            const __nv_bfloat16* asrc = pl ? g_xlo : g_xhi;                            \
            const __nv_bfloat16* bsrc = pl ? g_wlo : g_whi;                            \
            _Pragma("unroll")                                                          \
            for (int it = 0; it < 2; it++) {                                           \
                int r = r0 + it * 64;                                                  \
                uint32_t da = sb + (((stage) * 2 + pl) * 128 + r) * GSTRIDE + c0 * 16; \
                int grow = rowBase + r;                                                \
                cpa16(da, asrc + (size_t)grow * FDIM + _k0 + c0 * 8,                   \
                      grow < N_NODES ? 16 : 0);                                        \
                uint32_t db = da + B_BASE;                                             \
                cpa16(db, bsrc + (size_t)(colBase + r) * FDIM + _k0 + c0 * 8, 16);     \
            }                                                                          \
        }                                                                              \
    } while (0)

    LOAD_CHUNK(0, 0);
    CPA_COMMIT();

    for (int kc = 0; kc < 8; kc++) {
        int stage = kc & 1;
        if (kc < 7) { LOAD_CHUNK(kc + 1, stage ^ 1); CPA_COMMIT(); cpa_wait<1>(); }
        else        { cpa_wait<0>(); }
        __syncthreads();

        #pragma unroll
        for (int ks = 0; ks < 2; ks++) {
            int kcol = ks * 16 + (lane >> 4) * 8;
            uint32_t afr[2][2][4];
            #pragma unroll
            for (int pl = 0; pl < 2; pl++)
                #pragma unroll
                for (int mf = 0; mf < 2; mf++) {
                    int mr = warp_m * 32 + mf * 16 + (lane & 15);
                    ldm_x4(afr[pl][mf],
                           sb + ((stage * 2 + pl) * 128 + mr) * GSTRIDE + kcol * 2);
                }
            uint32_t bfr[2][8][2];
            #pragma unroll
            for (int pl = 0; pl < 2; pl++)
                #pragma unroll
                for (int np = 0; np < 4; np++) {
                    uint32_t r4[4];
                    int nr = warp_n * 64 + np * 16 + (lane & 15);
                    ldm_x4(r4, sb + B_BASE
                               + ((stage * 2 + pl) * 128 + nr) * GSTRIDE + kcol * 2);
                    bfr[pl][np * 2][0]     = r4[0]; bfr[pl][np * 2][1]     = r4[2];
                    bfr[pl][np * 2 + 1][0] = r4[1]; bfr[pl][np * 2 + 1][1] = r4[3];
                }
            #pragma unroll
            for (int mf = 0; mf < 2; mf++)
                #pragma unroll
                for (int nf = 0; nf < 8; nf++) {
                    mma_bf16(acc[mf][nf], afr[0][mf], bfr[0][nf]);  // hi*hi
                    mma_bf16(acc[mf][nf], afr[0][mf], bfr[1][nf]);  // hi*lo
                    mma_bf16(acc[mf][nf], afr[1][mf], bfr[0][nf]);  // lo*hi
                }
        }
        __syncthreads();
    }

    // epilogue: fragment layout -> g_y
    #pragma unroll
    for (int mf = 0; mf < 2; mf++) {
        int ga = rowBase + warp_m * 32 + mf * 16 + (lane >> 2);
        int col = colBase + warp_n * 64 + (lane & 3) * 2;
        #pragma unroll
        for (int nf = 0; nf < 8; nf++) {
            if (ga < N_NODES)
                *(float2*)(g_y + (size_t)ga * FDIM + col + nf * 8)
                    = make_float2(acc[mf][nf][0], acc[mf][nf][1]);
            if (ga + 8 < N_NODES)
                *(float2*)(g_y + (size_t)(ga + 8) * FDIM + col + nf * 8)
                    = make_float2(acc[mf][nf][2], acc[mf][nf][3]);
        }
    }
}

// ================= aggregation ======================================================
__global__ void __launch_bounds__(256) k_agg(const float* __restrict__ bias,
                                             float* __restrict__ out) {
    __shared__ int   sc[256];
    __shared__ float sw[256];
    int i = blockIdx.x;
    int f = threadIdx.x;
    int s = g_rowptr[i], e = g_rowptr[i + 1];
    float acc = 0.0f;
    for (int t0 = s; t0 < e; t0 += 256) {
        int nt = min(256, e - t0);
        __syncthreads();
        if (f < nt) { sc[f] = g_cola[t0 + f]; sw[f] = g_wa[t0 + f]; }
        __syncthreads();
        #pragma unroll 4
        for (int j = 0; j < nt; j++)
            acc += sw[j] * g_y[((size_t)sc[j] << 8) + f];
    }
    out[((size_t)i << 8) + f] = acc + bias[f];
}

// ================= launch ===========================================================
extern "C" void kernel_launch(void* const* d_in, const int* in_sizes, int n_in,
                              void* d_out, int out_size) {
    const float* x = nullptr;
    const void*  ei = nullptr;
    const float* C = nullptr;
    const float* W = nullptr;
    const float* b = nullptr;
    for (int i = 0; i < n_in; i++) {
        switch (in_sizes[i]) {
            case 12800000: x  = (const float*)d_in[i]; break;
            case  1600000: ei = d_in[i];               break;
            case   800000: C  = (const float*)d_in[i]; break;
            case    65536: W  = (const float*)d_in[i]; break;
            case      256: b  = (const float*)d_in[i]; break;
            default: break;
        }
    }
    float* out = (float*)d_out;

    cudaFuncSetAttribute(k_gemm_mma, cudaFuncAttributeMaxDynamicSharedMemorySize, SM_GEMM);

    const int TB = 256;
    k_detect<<<1, 1024>>>((const int*)ei);
    k_zero<<<(N_NODES + TB - 1) / TB, TB>>>();
    k_cvt_w<<<(FDIM * FDIM + TB - 1) / TB, TB>>>(W);
    k_cvt_x<<<(N_NODES * FDIM / 4 + TB - 1) / TB, TB>>>((const float4*)x);
    k_deg<<<(N_EDGES + TB - 1) / TB, TB>>>(ei, C);
    k_dis<<<(N_NODES + TB - 1) / TB, TB>>>();
    k_scan<<<1, 1024>>>();
    k_scatter<<<(N_EDGES + TB - 1) / TB, TB>>>(ei, C);

    dim3 gg((N_NODES + 127) / 128, 2);
    k_gemm_mma<<<gg, 256, SM_GEMM>>>();

    k_agg<<<N_NODES, 256>>>(b, out);
}

// round 5
// speedup vs baseline: 2.0009x; 1.4931x over previous
#include <cuda_runtime.h>
#include <cuda_bf16.h>
#include <cstdint>
#include <cstddef>

#define N_NODES 50000
#define N_EDGES 800000
#define FDIM 256

// ================= device scratch ===================================================
__device__ int   g_is64;
__device__ float g_deg[N_NODES];
__device__ int   g_cnt[N_NODES];
__device__ int   g_rowptr[N_NODES + 1];
__device__ int   g_cursor[N_NODES];
__device__ int   g_cola[N_EDGES];
__device__ float g_wa[N_EDGES];
__device__ float g_y[(size_t)N_NODES * FDIM];            // y = x @ W^T (51.2 MB)
__device__ __nv_bfloat16 g_xhi[(size_t)N_NODES * FDIM];
__device__ __nv_bfloat16 g_xlo[(size_t)N_NODES * FDIM];
__device__ __nv_bfloat16 g_whi[FDIM * FDIM];             // [n][k]
__device__ __nv_bfloat16 g_wlo[FDIM * FDIM];

// ================= PTX helpers ======================================================
__device__ __forceinline__ uint32_t smem_u32(const void* p) {
    uint32_t a;
    asm("{ .reg .u64 t; cvta.to.shared.u64 t, %1; cvt.u32.u64 %0, t; }" : "=r"(a) : "l"(p));
    return a;
}
__device__ __forceinline__ void cpa16(uint32_t dst, const void* src, int src_sz) {
    asm volatile("cp.async.cg.shared.global [%0], [%1], 16, %2;"
                 :: "r"(dst), "l"(src), "r"(src_sz));
}
#define CPA_COMMIT() asm volatile("cp.async.commit_group;" ::: "memory")
template <int N>
__device__ __forceinline__ void cpa_wait() {
    asm volatile("cp.async.wait_group %0;" :: "n"(N) : "memory");
}
__device__ __forceinline__ void ldm_x4(uint32_t* r, uint32_t addr) {
    asm volatile("ldmatrix.sync.aligned.m8n8.x4.shared.b16 {%0,%1,%2,%3}, [%4];"
                 : "=r"(r[0]), "=r"(r[1]), "=r"(r[2]), "=r"(r[3]) : "r"(addr));
}
__device__ __forceinline__ void mma_bf16(float* d, const uint32_t* a, const uint32_t* b) {
    asm volatile("mma.sync.aligned.m16n8k16.row.col.f32.bf16.bf16.f32 "
                 "{%0,%1,%2,%3}, {%4,%5,%6,%7}, {%8,%9}, {%0,%1,%2,%3};"
                 : "+f"(d[0]), "+f"(d[1]), "+f"(d[2]), "+f"(d[3])
                 : "r"(a[0]), "r"(a[1]), "r"(a[2]), "r"(a[3]), "r"(b[0]), "r"(b[1]));
}

// ================= edge-index access ================================================
__device__ __forceinline__ int edge_at(const void* ei, int idx, int is64) {
    int v = is64 ? (int)((const long long*)ei)[idx] : ((const int*)ei)[idx];
    if ((unsigned)v >= (unsigned)N_NODES) v = 0;
    return v;
}

// ================= graph-side kernels ==============================================
__global__ void k_detect(const int* __restrict__ w) {
    __shared__ int cnt;
    int t = threadIdx.x;
    if (t == 0) cnt = 0;
    __syncthreads();
    if (w[2 * t + 1] == 0) atomicAdd(&cnt, 1);
    __syncthreads();
    if (t == 0) g_is64 = (cnt > 900) ? 1 : 0;
}

__global__ void k_zero() {
    int i = blockIdx.x * blockDim.x + threadIdx.x;
    if (i < N_NODES) { g_deg[i] = 0.0f; g_cnt[i] = 0; }
}

__global__ void k_deg(const void* __restrict__ ei, const float* __restrict__ C) {
    int e = blockIdx.x * blockDim.x + threadIdx.x;
    if (e < N_EDGES) {
        int is64 = g_is64;
        int r = edge_at(ei, e, is64);
        atomicAdd(&g_deg[r], C[e]);
        atomicAdd(&g_cnt[r], 1);
    }
}

__global__ void k_dis() {
    int i = blockIdx.x * blockDim.x + threadIdx.x;
    if (i < N_NODES) {
        float d = g_deg[i];
        g_deg[i] = (d > 0.0f) ? rsqrtf(d) : 0.0f;
    }
}

// warp-shuffle hierarchical scan, single block of 1024
__global__ void k_scan() {
    __shared__ int wsum[32];
    int t = threadIdx.x, lane = t & 31, wid = t >> 5;
    int carry = 0;
    for (int base = 0; base < N_NODES; base += 1024) {
        int idx = base + t;
        int v = (idx < N_NODES) ? g_cnt[idx] : 0;
        int inc = v;
        #pragma unroll
        for (int off = 1; off < 32; off <<= 1) {
            int n = __shfl_up_sync(0xFFFFFFFFu, inc, off);
            if (lane >= off) inc += n;
        }
        if (lane == 31) wsum[wid] = inc;
        __syncthreads();
        if (wid == 0) {
            int s = wsum[lane];
            #pragma unroll
            for (int off = 1; off < 32; off <<= 1) {
                int n = __shfl_up_sync(0xFFFFFFFFu, s, off);
                if (lane >= off) s += n;
            }
            wsum[lane] = s;
        }
        __syncthreads();
        int woff = (wid > 0) ? wsum[wid - 1] : 0;
        int excl = carry + woff + inc - v;
        if (idx < N_NODES) { g_rowptr[idx] = excl; g_cursor[idx] = excl; }
        carry += wsum[31];
        __syncthreads();
    }
    if (t == 0) g_rowptr[N_NODES] = carry;
}

__global__ void k_scatter(const void* __restrict__ ei, const float* __restrict__ C) {
    int e = blockIdx.x * blockDim.x + threadIdx.x;
    if (e < N_EDGES) {
        int is64 = g_is64;
        int r = edge_at(ei, e, is64);
        int c = edge_at(ei, N_EDGES + e, is64);
        float w = g_deg[r] * C[e] * g_deg[c];
        int p = atomicAdd(&g_cursor[r], 1);
        g_cola[p] = c;
        g_wa[p]   = w;
    }
}

// ================= bf16 hi/lo conversions ==========================================
__global__ void k_cvt_x(const float4* __restrict__ X) {
    int i = blockIdx.x * blockDim.x + threadIdx.x;
    if (i < (N_NODES * FDIM) / 4) {
        float4 v = X[i];
        float f[4] = {v.x, v.y, v.z, v.w};
        ushort4 hv, lv;
        unsigned short* hp = &hv.x;
        unsigned short* lp = &lv.x;
        #pragma unroll
        for (int j = 0; j < 4; j++) {
            __nv_bfloat16 h = __float2bfloat16_rn(f[j]);
            __nv_bfloat16 l = __float2bfloat16_rn(f[j] - __bfloat162float(h));
            hp[j] = *(unsigned short*)&h;
            lp[j] = *(unsigned short*)&l;
        }
        ((ushort4*)g_xhi)[i] = hv;
        ((ushort4*)g_xlo)[i] = lv;
    }
}

__global__ void k_cvt_w(const float* __restrict__ W) {
    int idx = blockIdx.x * blockDim.x + threadIdx.x;
    if (idx < FDIM * FDIM) {
        float w = W[idx];
        __nv_bfloat16 h = __float2bfloat16_rn(w);
        __nv_bfloat16 l = __float2bfloat16_rn(w - __bfloat162float(h));
        g_whi[idx] = h;
        g_wlo[idx] = l;
    }
}

// ================= HMMA GEMM: y = x @ W^T (bf16 hi/lo, m16n8k16) ====================
// grid (391, 2), block 256 (8 warps: warp_m=wid&3 -> 32 rows, warp_n=wid>>2 -> 64 cols)
// smem: A [2 stages][2 planes][128 rows][stride 80B], B same at +40960. Total 80 KB.
// 80KB x 2 CTAs = 160KB fits the 228KB carveout -> occupancy 2.
#define GSTRIDE 80
#define B_BASE  40960
#define SM_GEMM 81920

__global__ void __launch_bounds__(256) k_gemm_mma() {
    extern __shared__ __align__(128) unsigned char sm[];
    uint32_t sb = smem_u32(sm);
    int tid = threadIdx.x, wid = tid >> 5, lane = tid & 31;
    int warp_m = wid & 3, warp_n = wid >> 2;
    int rowBase = blockIdx.x * 128, colBase = blockIdx.y * 128;

    float acc[2][8][4];
    #pragma unroll
    for (int a = 0; a < 2; a++)
        #pragma unroll
        for (int b = 0; b < 8; b++)
            #pragma unroll
            for (int c = 0; c < 4; c++) acc[a][b][c] = 0.0f;

    int r0 = tid >> 2, c0 = tid & 3;

    #define LOAD_CHUNK(kc, stage)                                                      \
    do {                                                                               \
        int _k0 = (kc) * 32;                                                           \
        _Pragma("unroll")                                                              \
        for (int pl = 0; pl < 2; pl++) {                                               \
            const __nv_bfloat16* asrc = pl ? g_xlo : g_xhi;                            \
            const __nv_bfloat16* bsrc = pl ? g_wlo : g_whi;                            \
            _Pragma("unroll")                                                          \
            for (int it = 0; it < 2; it++) {                                           \
                int r = r0 + it * 64;                                                  \
                uint32_t da = sb + (((stage) * 2 + pl) * 128 + r) * GSTRIDE + c0 * 16; \
                int grow = rowBase + r;                                                \
                cpa16(da, asrc + (size_t)grow * FDIM + _k0 + c0 * 8,                   \
                      grow < N_NODES ? 16 : 0);                                        \
                uint32_t db = da + B_BASE;                                             \
                cpa16(db, bsrc + (size_t)(colBase + r) * FDIM + _k0 + c0 * 8, 16);     \
            }                                                                          \
        }                                                                              \
    } while (0)

    LOAD_CHUNK(0, 0);
    CPA_COMMIT();

    for (int kc = 0; kc < 8; kc++) {
        int stage = kc & 1;
        if (kc < 7) { LOAD_CHUNK(kc + 1, stage ^ 1); CPA_COMMIT(); cpa_wait<1>(); }
        else        { cpa_wait<0>(); }
        __syncthreads();

        #pragma unroll
        for (int ks = 0; ks < 2; ks++) {
            int kcol = ks * 16 + (lane >> 4) * 8;
            uint32_t afr[2][2][4];
            #pragma unroll
            for (int pl = 0; pl < 2; pl++)
                #pragma unroll
                for (int mf = 0; mf < 2; mf++) {
                    int mr = warp_m * 32 + mf * 16 + (lane & 15);
                    ldm_x4(afr[pl][mf],
                           sb + ((stage * 2 + pl) * 128 + mr) * GSTRIDE + kcol * 2);
                }
            uint32_t bfr[2][8][2];
            #pragma unroll
            for (int pl = 0; pl < 2; pl++)
                #pragma unroll
                for (int np = 0; np < 4; np++) {
                    uint32_t r4[4];
                    int nr = warp_n * 64 + np * 16 + (lane & 15);
                    ldm_x4(r4, sb + B_BASE
                               + ((stage * 2 + pl) * 128 + nr) * GSTRIDE + kcol * 2);
                    bfr[pl][np * 2][0]     = r4[0]; bfr[pl][np * 2][1]     = r4[2];
                    bfr[pl][np * 2 + 1][0] = r4[1]; bfr[pl][np * 2 + 1][1] = r4[3];
                }
            #pragma unroll
            for (int mf = 0; mf < 2; mf++)
                #pragma unroll
                for (int nf = 0; nf < 8; nf++) {
                    mma_bf16(acc[mf][nf], afr[0][mf], bfr[0][nf]);  // hi*hi
                    mma_bf16(acc[mf][nf], afr[0][mf], bfr[1][nf]);  // hi*lo
                    mma_bf16(acc[mf][nf], afr[1][mf], bfr[0][nf]);  // lo*hi
                }
        }
        __syncthreads();
    }

    // epilogue: fragment layout -> g_y
    #pragma unroll
    for (int mf = 0; mf < 2; mf++) {
        int ga = rowBase + warp_m * 32 + mf * 16 + (lane >> 2);
        int col = colBase + warp_n * 64 + (lane & 3) * 2;
        #pragma unroll
        for (int nf = 0; nf < 8; nf++) {
            if (ga < N_NODES)
                *(float2*)(g_y + (size_t)ga * FDIM + col + nf * 8)
                    = make_float2(acc[mf][nf][0], acc[mf][nf][1]);
            if (ga + 8 < N_NODES)
                *(float2*)(g_y + (size_t)(ga + 8) * FDIM + col + nf * 8)
                    = make_float2(acc[mf][nf][2], acc[mf][nf][3]);
        }
    }
}

// ================= aggregation: 128 threads, float2 per thread ======================
__global__ void __launch_bounds__(128) k_agg(const float* __restrict__ bias,
                                             float* __restrict__ out) {
    __shared__ int   sc[128];
    __shared__ float sw[128];
    int i = blockIdx.x;
    int f = threadIdx.x;                 // feature pair index 0..127
    int s = g_rowptr[i], e = g_rowptr[i + 1];
    float ax = 0.0f, ay = 0.0f;
    const float2* Y = (const float2*)g_y;
    for (int t0 = s; t0 < e; t0 += 128) {
        int nt = min(128, e - t0);
        __syncthreads();
        if (f < nt) { sc[f] = g_cola[t0 + f]; sw[f] = g_wa[t0 + f]; }
        __syncthreads();
        #pragma unroll 4
        for (int j = 0; j < nt; j++) {
            float w = sw[j];
            float2 v = Y[((size_t)sc[j] << 7) + f];
            ax += w * v.x;
            ay += w * v.y;
        }
    }
    float2 bb = ((const float2*)bias)[f];
    ((float2*)out)[((size_t)i << 7) + f] = make_float2(ax + bb.x, ay + bb.y);
}

// ================= launch: fork-join two-stream graph ===============================
extern "C" void kernel_launch(void* const* d_in, const int* in_sizes, int n_in,
                              void* d_out, int out_size) {
    const float* x = nullptr;
    const void*  ei = nullptr;
    const float* C = nullptr;
    const float* W = nullptr;
    const float* b = nullptr;
    for (int i = 0; i < n_in; i++) {
        switch (in_sizes[i]) {
            case 12800000: x  = (const float*)d_in[i]; break;
            case  1600000: ei = d_in[i];               break;
            case   800000: C  = (const float*)d_in[i]; break;
            case    65536: W  = (const float*)d_in[i]; break;
            case      256: b  = (const float*)d_in[i]; break;
            default: break;
        }
    }
    float* out = (float*)d_out;

    // one-time host-side resources (created on the uncaptured correctness call)
    static cudaStream_t s2 = nullptr;
    static cudaEvent_t evFork = nullptr, evJoin = nullptr;
    if (s2 == nullptr) {
        cudaStreamCreateWithFlags(&s2, cudaStreamNonBlocking);
        cudaEventCreateWithFlags(&evFork, cudaEventDisableTiming);
        cudaEventCreateWithFlags(&evJoin, cudaEventDisableTiming);
    }
    cudaFuncSetAttribute(k_gemm_mma, cudaFuncAttributeMaxDynamicSharedMemorySize, SM_GEMM);

    const int TB = 256;

    // fork: CSR chain on s2
    cudaEventRecord(evFork, 0);
    cudaStreamWaitEvent(s2, evFork, 0);
    k_detect<<<1, 1024, 0, s2>>>((const int*)ei);
    k_zero<<<(N_NODES + TB - 1) / TB, TB, 0, s2>>>();
    k_deg<<<(N_EDGES + TB - 1) / TB, TB, 0, s2>>>(ei, C);
    k_dis<<<(N_NODES + TB - 1) / TB, TB, 0, s2>>>();
    k_scan<<<1, 1024, 0, s2>>>();
    k_scatter<<<(N_EDGES + TB - 1) / TB, TB, 0, s2>>>(ei, C);
    cudaEventRecord(evJoin, s2);

    // main stream: dense chain
    k_cvt_w<<<(FDIM * FDIM + TB - 1) / TB, TB>>>(W);
    k_cvt_x<<<(N_NODES * FDIM / 4 + TB - 1) / TB, TB>>>((const float4*)x);
    dim3 gg((N_NODES + 127) / 128, 2);
    k_gemm_mma<<<gg, 256, SM_GEMM>>>();

    // join, then aggregate
    cudaStreamWaitEvent(0, evJoin, 0);
    k_agg<<<N_NODES, 128>>>(b, out);
}